// round 7
// baseline (speedup 1.0000x reference)
#include <cuda_runtime.h>
#include <cuda_fp16.h>

#define NUM_USERS 30000
#define NN 60000            // total nodes
#define EE 800000           // edges
#define KK 64               // embed dim (4 intents x 16)
#define NCHUNK 235          // ceil(NN/256) scan chunks

// -------- device scratch --------
__device__ __half d_TT16[(size_t)NN * KK];   // fp16 tanh(per-intent l2norm(ego))
__device__ __half d_EGO16[(size_t)NN * KK];  // fp16 rs1[n]*ego[n]
__device__ float  d_SC[(size_t)EE * 4];      // softmax scores at SORTED edge pos
__device__ int    d_deg[NN];
__device__ float  d_deg2[NN * 4];            // node-major [n][intent]
__device__ int    d_rowptr[NN + 1];
__device__ int    d_cursor[NN];
__device__ int    d_sorted_t[EE];            // tails grouped by head
__device__ int    d_partial[NCHUNK];         // scan chunk sums
__device__ unsigned d_bar = 0;               // monotonic grid-barrier counter

__device__ __forceinline__ const float4* ego_row(const float* Gu, const float* Gi, int t) {
    const float* p = (t < NUM_USERS) ? (Gu + (size_t)t * KK)
                                     : (Gi + (size_t)(t - NUM_USERS) * KK);
    return reinterpret_cast<const float4*>(p);
}

__device__ __forceinline__ float4 h4_to_f4(uint2 p) {
    float2 a = __half22float2(*reinterpret_cast<const __half2*>(&p.x));
    float2 b = __half22float2(*reinterpret_cast<const __half2*>(&p.y));
    return make_float4(a.x, a.y, b.x, b.y);
}

__device__ __forceinline__ float fast_tanh(float x) {   // |x|<=1 here; no overflow
    float e = __expf(2.f * x);
    return __fdividef(e - 1.f, e + 1.f);
}

// softmax over intents; "1+" and max-shift cancel algebraically (|logit|<=4).
__device__ __forceinline__ float edge_attn(float4 hv, float4 b, unsigned hm) {
    float p = hv.x * b.x + hv.y * b.y + hv.z * b.z + hv.w * b.w;
    p += __shfl_xor_sync(hm, p, 1);
    p += __shfl_xor_sync(hm, p, 2);
    float ex = __expf(p);
    float sum = ex + __shfl_xor_sync(hm, ex, 4);
    sum += __shfl_xor_sync(hm, sum, 8);
    return __fdividef(ex, sum);
}

// monotonic-counter grid barrier: replay-safe (no reset), all blocks co-resident.
__device__ __forceinline__ void gridbar() {
    __syncthreads();
    if (threadIdx.x == 0) {
        __threadfence();                                  // release prior writes
        unsigned token = atomicAdd(&d_bar, 1u);
        unsigned target = (token / gridDim.x + 1u) * gridDim.x;
        unsigned v;
        do {
            asm volatile("ld.acquire.gpu.global.u32 %0, [%1];"
                         : "=r"(v) : "l"(&d_bar) : "memory");
            if (v < target) __nanosleep(32);
        } while (v < target);
    }
    __syncthreads();
}

// block-wide exclusive scan (blockDim=256)
__device__ __forceinline__ int block_exscan(int v, int* sm) {
    int lane = threadIdx.x & 31, w = threadIdx.x >> 5;
    int x = v;
#pragma unroll
    for (int d = 1; d < 32; d <<= 1) {
        int y = __shfl_up_sync(0xffffffffu, x, d);
        if (lane >= d) x += y;
    }
    if (lane == 31) sm[w] = x;
    __syncthreads();
    if (w == 0) {
        int s = (lane < 8) ? sm[lane] : 0;
#pragma unroll
        for (int d = 1; d < 8; d <<= 1) {
            int y = __shfl_up_sync(0xffffffffu, s, d);
            if (lane >= d) s += y;
        }
        if (lane < 8) sm[lane] = s;
    }
    __syncthreads();
    int off = (w > 0) ? sm[w - 1] : 0;
    return off + x - v;
}

__global__ void __launch_bounds__(256, 6)
k_fused(const float* __restrict__ Gu, const float* __restrict__ Gi,
        const int* __restrict__ eh, const int* __restrict__ et,
        float* __restrict__ out) {
    __shared__ int sm[8];
    __shared__ int sh_base;
    const int tid  = blockIdx.x * 256 + threadIdx.x;
    const int nthr = gridDim.x * 256;

    // ---- P0: zero deg + TT16 = fp16 tanh(per-intent l2norm(ego)) ----
    for (int i = tid; i < NN; i += nthr) d_deg[i] = 0;
    for (int i = tid; i < NN * 16; i += nthr) {
        int n = i >> 4, c = i & 15;
        float4 v = __ldg(&ego_row(Gu, Gi, n)[c]);
        float ss = v.x * v.x + v.y * v.y + v.z * v.z + v.w * v.w;
        ss += __shfl_xor_sync(0xffffffffu, ss, 1);
        ss += __shfl_xor_sync(0xffffffffu, ss, 2);
        float it = rsqrtf(fmaxf(ss, 1e-12f));
        __half2 t0 = __floats2half2_rn(fast_tanh(v.x * it), fast_tanh(v.y * it));
        __half2 t1 = __floats2half2_rn(fast_tanh(v.z * it), fast_tanh(v.w * it));
        uint2 tp; tp.x = *reinterpret_cast<unsigned*>(&t0);
                  tp.y = *reinterpret_cast<unsigned*>(&t1);
        reinterpret_cast<uint2*>(d_TT16)[i] = tp;
        (void)c;
    }
    gridbar();

    // ---- P1: head degree count ----
    for (int g = tid; g < EE / 4; g += nthr) {
        int4 h4 = __ldg(&reinterpret_cast<const int4*>(eh)[g]);
        atomicAdd(&d_deg[h4.x], 1);
        atomicAdd(&d_deg[h4.y], 1);
        atomicAdd(&d_deg[h4.z], 1);
        atomicAdd(&d_deg[h4.w], 1);
    }
    gridbar();

    // ---- P2: per-chunk local scans + EGO16 (needs final deg) ----
    for (int vb = blockIdx.x; vb < NCHUNK; vb += gridDim.x) {
        int i = vb * 256 + threadIdx.x;
        int v = (i < NN) ? d_deg[i] : 0;
        int ex = block_exscan(v, sm);
        if (i < NN) d_rowptr[i] = ex;       // local (chunk) exclusive scan
        if (threadIdx.x == 255) d_partial[vb] = ex + v;
        __syncthreads();                    // protect sm reuse across iterations
    }
    for (int i = tid; i < NN * 16; i += nthr) {
        int n = i >> 4, c = i & 15;
        float4 v = __ldg(&ego_row(Gu, Gi, n)[c]);
        float w = rsqrtf((float)d_deg[n]);  // rs1 folded into EGO16
        __half2 e0 = __floats2half2_rn(w * v.x, w * v.y);
        __half2 e1 = __floats2half2_rn(w * v.z, w * v.w);
        uint2 ep; ep.x = *reinterpret_cast<unsigned*>(&e0);
                  ep.y = *reinterpret_cast<unsigned*>(&e1);
        reinterpret_cast<uint2*>(d_EGO16)[i] = ep;
    }
    gridbar();

    // ---- P3: add chunk bases -> final rowptr + cursor ----
    for (int vb = blockIdx.x; vb < NCHUNK; vb += gridDim.x) {
        if (threadIdx.x < 32) {
            int s = 0;
            for (int t2 = threadIdx.x; t2 < vb; t2 += 32) s += d_partial[t2];
#pragma unroll
            for (int d = 16; d >= 1; d >>= 1) s += __shfl_xor_sync(0xffffffffu, s, d);
            if (threadIdx.x == 0) sh_base = s;
        }
        __syncthreads();
        int i = vb * 256 + threadIdx.x;
        if (i < NN) { int r = d_rowptr[i] + sh_base; d_rowptr[i] = r; d_cursor[i] = r; }
        __syncthreads();
    }
    if (tid == 0) d_rowptr[NN] = EE;
    gridbar();

    // ---- P4: scatter tails into head-grouped order ----
    for (int g = tid; g < EE / 4; g += nthr) {
        int4 h4 = __ldg(&reinterpret_cast<const int4*>(eh)[g]);
        int4 t4 = __ldg(&reinterpret_cast<const int4*>(et)[g]);
        d_sorted_t[atomicAdd(&d_cursor[h4.x], 1)] = t4.x;
        d_sorted_t[atomicAdd(&d_cursor[h4.y], 1)] = t4.y;
        d_sorted_t[atomicAdd(&d_cursor[h4.z], 1)] = t4.z;
        d_sorted_t[atomicAdd(&d_cursor[h4.w], 1)] = t4.w;
    }
    gridbar();

    // ---- P5: warp-per-row SpMM1 + l2norm + attention + softmax + deg2 ----
    {
        int gw = tid >> 5, nw = nthr >> 5;
        int lane = threadIdx.x & 31, half = lane >> 4, c = lane & 15;
        unsigned hm = half ? 0xFFFF0000u : 0x0000FFFFu;
        const uint2* EG = reinterpret_cast<const uint2*>(d_EGO16);
        const uint2* TT = reinterpret_cast<const uint2*>(d_TT16);
        for (int wid = gw; wid < NN; wid += nw) {
            int start = d_rowptr[wid], end = d_rowptr[wid + 1];
            float4 acc = make_float4(0, 0, 0, 0);
            int j = start + half;
            for (; j + 2 < end; j += 4) {
                int t0 = __ldg(&d_sorted_t[j]);
                int t1 = __ldg(&d_sorted_t[j + 2]);
                float4 s0 = h4_to_f4(__ldg(&EG[(size_t)t0 * 16 + c]));
                float4 s1 = h4_to_f4(__ldg(&EG[(size_t)t1 * 16 + c]));
                acc.x += s0.x + s1.x; acc.y += s0.y + s1.y;
                acc.z += s0.z + s1.z; acc.w += s0.w + s1.w;
            }
            if (j < end) {
                int t = __ldg(&d_sorted_t[j]);
                float4 s = h4_to_f4(__ldg(&EG[(size_t)t * 16 + c]));
                acc.x += s.x; acc.y += s.y; acc.z += s.z; acc.w += s.w;
            }
            acc.x += __shfl_xor_sync(0xffffffffu, acc.x, 16);
            acc.y += __shfl_xor_sync(0xffffffffu, acc.y, 16);
            acc.z += __shfl_xor_sync(0xffffffffu, acc.z, 16);
            acc.w += __shfl_xor_sync(0xffffffffu, acc.w, 16);
            float ss = acc.x * acc.x + acc.y * acc.y + acc.z * acc.z + acc.w * acc.w;
            ss += __shfl_xor_sync(0xffffffffu, ss, 1);
            ss += __shfl_xor_sync(0xffffffffu, ss, 2);
            float ih = rsqrtf(fmaxf(ss, 1e-12f));
            float4 hv = make_float4(acc.x * ih, acc.y * ih, acc.z * ih, acc.w * ih);

            float dsum = 0.f;
            j = start + half;
            for (; j + 2 < end; j += 4) {
                int t0 = __ldg(&d_sorted_t[j]);
                int t1 = __ldg(&d_sorted_t[j + 2]);
                float4 b0 = h4_to_f4(__ldg(&TT[(size_t)t0 * 16 + c]));
                float4 b1 = h4_to_f4(__ldg(&TT[(size_t)t1 * 16 + c]));
                float sc0 = edge_attn(hv, b0, hm);
                float sc1 = edge_attn(hv, b1, hm);
                if ((c & 3) == 0) {
                    int i4 = c >> 2;
                    d_SC[(size_t)j * 4 + i4] = sc0;
                    d_SC[(size_t)(j + 2) * 4 + i4] = sc1;
                    dsum += sc0 + sc1;
                }
            }
            if (j < end) {
                int t = __ldg(&d_sorted_t[j]);
                float4 b = h4_to_f4(__ldg(&TT[(size_t)t * 16 + c]));
                float sc = edge_attn(hv, b, hm);
                if ((c & 3) == 0) {
                    d_SC[(size_t)j * 4 + (c >> 2)] = sc;
                    dsum += sc;
                }
            }
            dsum += __shfl_xor_sync(0xffffffffu, dsum, 16);
            if (half == 0 && (c & 3) == 0)
                d_deg2[wid * 4 + (c >> 2)] = dsum;
        }
    }
    gridbar();

    // ---- P6: warp-per-row SpMM2 + rs2 + final mean -> out ----
    {
        int gw = tid >> 5, nw = nthr >> 5;
        int lane = threadIdx.x & 31, half = lane >> 4, c = lane & 15;
        int intent = c >> 2;
        for (int wid = gw; wid < NN; wid += nw) {
            int start = d_rowptr[wid], end = d_rowptr[wid + 1];
            float4 acc = make_float4(0, 0, 0, 0);
            int j = start + half;
            for (; j + 2 < end; j += 4) {
                int t0 = __ldg(&d_sorted_t[j]);
                int t1 = __ldg(&d_sorted_t[j + 2]);
                float w0 = __ldg(&d_SC[(size_t)j * 4 + intent]) *
                           rsqrtf(__ldg(&d_deg2[t0 * 4 + intent]));
                float w1 = __ldg(&d_SC[(size_t)(j + 2) * 4 + intent]) *
                           rsqrtf(__ldg(&d_deg2[t1 * 4 + intent]));
                float4 s0 = __ldg(&ego_row(Gu, Gi, t0)[c]);
                float4 s1 = __ldg(&ego_row(Gu, Gi, t1)[c]);
                acc.x += w0 * s0.x + w1 * s1.x;
                acc.y += w0 * s0.y + w1 * s1.y;
                acc.z += w0 * s0.z + w1 * s1.z;
                acc.w += w0 * s0.w + w1 * s1.w;
            }
            if (j < end) {
                int t = __ldg(&d_sorted_t[j]);
                float w = __ldg(&d_SC[(size_t)j * 4 + intent]) *
                          rsqrtf(__ldg(&d_deg2[t * 4 + intent]));
                float4 s = __ldg(&ego_row(Gu, Gi, t)[c]);
                acc.x += w * s.x; acc.y += w * s.y; acc.z += w * s.z; acc.w += w * s.w;
            }
            acc.x += __shfl_xor_sync(0xffffffffu, acc.x, 16);
            acc.y += __shfl_xor_sync(0xffffffffu, acc.y, 16);
            acc.z += __shfl_xor_sync(0xffffffffu, acc.z, 16);
            acc.w += __shfl_xor_sync(0xffffffffu, acc.w, 16);
            if (half == 0) {
                float r2 = rsqrtf(d_deg2[wid * 4 + intent]);
                float4 a = __ldg(&ego_row(Gu, Gi, wid)[c]);
                reinterpret_cast<float4*>(out)[(size_t)wid * 16 + c] =
                    make_float4(0.5f * (a.x + r2 * acc.x), 0.5f * (a.y + r2 * acc.y),
                                0.5f * (a.z + r2 * acc.z), 0.5f * (a.w + r2 * acc.w));
            }
        }
    }
}

extern "C" void kernel_launch(void* const* d_in, const int* in_sizes, int n_in,
                              void* d_out, int out_size) {
    const float* Gu = (const float*)d_in[0];
    const float* Gi = (const float*)d_in[1];
    const int*   eh = (const int*)d_in[2];
    const int*   et = (const int*)d_in[3];
    float* out = (float*)d_out;

    // size grid to guaranteed co-residency (grid barrier safety)
    int dev = 0;
    cudaGetDevice(&dev);
    int smCount = 0;
    cudaDeviceGetAttribute(&smCount, cudaDevAttrMultiProcessorCount, dev);
    int nb = 0;
    cudaOccupancyMaxActiveBlocksPerMultiprocessor(&nb, k_fused, 256, 0);
    if (nb < 1) nb = 1;
    if (nb > 6) nb = 6;

    k_fused<<<smCount * nb, 256>>>(Gu, Gi, eh, et, out);
}

// round 8
// speedup vs baseline: 1.2935x; 1.2935x over previous
#include <cuda_runtime.h>
#include <cuda_fp16.h>

#define NUM_USERS 30000
#define NN 60000            // total nodes
#define EE 800000           // edges
#define KK 64               // embed dim (4 intents x 16)
#define NB 235              // ceil(NN/256) scan blocks

// -------- device scratch --------
__device__ __half d_TT16[(size_t)NN * KK];   // fp16 tanh(per-intent l2norm(ego))
__device__ __half d_EGO16[(size_t)NN * KK];  // fp16 rs1[n]*ego[n]  (attention path)
__device__ float  d_SC[(size_t)EE * 4];      // softmax scores at SORTED edge pos
__device__ int    d_deg[NN];
__device__ float  d_deg2[NN * 4];            // node-major [n][intent]
__device__ int    d_rowptr[NN + 1];
__device__ int    d_cursor[NN];
__device__ int    d_sorted_t[EE];            // tails grouped by head
__device__ int    d_partial[256];            // scan block sums

__device__ __forceinline__ const float4* ego_row(const float* Gu, const float* Gi, int t) {
    const float* p = (t < NUM_USERS) ? (Gu + (size_t)t * KK)
                                     : (Gi + (size_t)(t - NUM_USERS) * KK);
    return reinterpret_cast<const float4*>(p);
}

__device__ __forceinline__ float4 h4_to_f4(uint2 p) {
    float2 a = __half22float2(*reinterpret_cast<const __half2*>(&p.x));
    float2 b = __half22float2(*reinterpret_cast<const __half2*>(&p.y));
    return make_float4(a.x, a.y, b.x, b.y);
}

__device__ __forceinline__ float fast_tanh(float x) {   // |x|<=1 here
    float e = __expf(2.f * x);
    return __fdividef(e - 1.f, e + 1.f);
}

// block-wide exclusive scan of one int per thread (blockDim=256)
__device__ __forceinline__ int block_exscan(int v, int* sm) {
    int lane = threadIdx.x & 31, w = threadIdx.x >> 5;
    int x = v;
#pragma unroll
    for (int d = 1; d < 32; d <<= 1) {
        int y = __shfl_up_sync(0xffffffffu, x, d);
        if (lane >= d) x += y;
    }
    if (lane == 31) sm[w] = x;
    __syncthreads();
    if (w == 0) {
        int s = (lane < 8) ? sm[lane] : 0;
#pragma unroll
        for (int d = 1; d < 8; d <<= 1) {
            int y = __shfl_up_sync(0xffffffffu, s, d);
            if (lane >= d) s += y;
        }
        if (lane < 8) sm[lane] = s;
    }
    __syncthreads();
    int off = (w > 0) ? sm[w - 1] : 0;
    return off + x - v;
}

// -------- kernels --------

__global__ void k_deg(const int* __restrict__ eh) {
    int g = blockIdx.x * blockDim.x + threadIdx.x;
    if (g >= EE / 4) return;
    int4 h4 = reinterpret_cast<const int4*>(eh)[g];
    atomicAdd(&d_deg[h4.x], 1);
    atomicAdd(&d_deg[h4.y], 1);
    atomicAdd(&d_deg[h4.z], 1);
    atomicAdd(&d_deg[h4.w], 1);
}

__global__ void k_s1() {
    __shared__ int sm[8];
    int i = blockIdx.x * 256 + threadIdx.x;
    int v = (i < NN) ? d_deg[i] : 0;
    int ex = block_exscan(v, sm);
    if (threadIdx.x == 255) d_partial[blockIdx.x] = ex + v;
}

__global__ void k_scan() {
    __shared__ int sm[8];
    __shared__ int base_sh;
    if (threadIdx.x < 32) {
        int s = 0;
        for (int t = threadIdx.x; t < blockIdx.x; t += 32) s += d_partial[t];
#pragma unroll
        for (int d = 16; d >= 1; d >>= 1) s += __shfl_xor_sync(0xffffffffu, s, d);
        if (threadIdx.x == 0) base_sh = s;
    }
    int i = blockIdx.x * 256 + threadIdx.x;
    int v = (i < NN) ? d_deg[i] : 0;
    int ex = block_exscan(v, sm);           // has __syncthreads (publishes base_sh)
    ex += base_sh;
    if (i < NN) { d_rowptr[i] = ex; d_cursor[i] = ex; }
    if (i == NN - 1) d_rowptr[NN] = EE;
}

#define SCAT_BLKS ((EE / 4 + 255) / 256)
#define NODE_BLKS ((NN * 16 + 255) / 256)

// fused: blocks [0, SCAT_BLKS) scatter tails; rest compute TT16 + EGO16
__global__ void k_scatter_node(const int* __restrict__ eh, const int* __restrict__ et,
                               const float* __restrict__ Gu, const float* __restrict__ Gi) {
    if (blockIdx.x < SCAT_BLKS) {
        int g = blockIdx.x * blockDim.x + threadIdx.x;
        if (g >= EE / 4) return;
        int4 h4 = __ldg(&reinterpret_cast<const int4*>(eh)[g]);
        int4 t4 = __ldg(&reinterpret_cast<const int4*>(et)[g]);
        d_sorted_t[atomicAdd(&d_cursor[h4.x], 1)] = t4.x;
        d_sorted_t[atomicAdd(&d_cursor[h4.y], 1)] = t4.y;
        d_sorted_t[atomicAdd(&d_cursor[h4.z], 1)] = t4.z;
        d_sorted_t[atomicAdd(&d_cursor[h4.w], 1)] = t4.w;
    } else {
        int tid = (blockIdx.x - SCAT_BLKS) * blockDim.x + threadIdx.x;
        if (tid >= NN * 16) return;
        int n = tid >> 4;
        float4 v = __ldg(&ego_row(Gu, Gi, n)[tid & 15]);
        float ss = v.x * v.x + v.y * v.y + v.z * v.z + v.w * v.w;
        ss += __shfl_xor_sync(0xffffffffu, ss, 1);
        ss += __shfl_xor_sync(0xffffffffu, ss, 2);
        float it = rsqrtf(fmaxf(ss, 1e-12f));
        __half2 t0 = __floats2half2_rn(fast_tanh(v.x * it), fast_tanh(v.y * it));
        __half2 t1 = __floats2half2_rn(fast_tanh(v.z * it), fast_tanh(v.w * it));
        uint2 tp; tp.x = *reinterpret_cast<unsigned*>(&t0);
                  tp.y = *reinterpret_cast<unsigned*>(&t1);
        reinterpret_cast<uint2*>(d_TT16)[tid] = tp;
        float w = rsqrtf((float)d_deg[n]);   // rs1 folded into EGO16
        __half2 e0 = __floats2half2_rn(w * v.x, w * v.y);
        __half2 e1 = __floats2half2_rn(w * v.z, w * v.w);
        uint2 ep; ep.x = *reinterpret_cast<unsigned*>(&e0);
                  ep.y = *reinterpret_cast<unsigned*>(&e1);
        reinterpret_cast<uint2*>(d_EGO16)[tid] = ep;
    }
}

// Warp-per-row: SpMM1 (halves layout) -> per-intent l2norm -> transpose hv ->
// attention pass in (slot,intent) layout: 8 edges x 4 intents per warp-iter,
// each lane computes one (edge,intent) dot serially in fp32 registers.
__global__ void k_row1attn() {
    int wid = (blockIdx.x * blockDim.x + threadIdx.x) >> 5;
    if (wid >= NN) return;
    int lane = threadIdx.x & 31, half = lane >> 4, c = lane & 15;
    int start = d_rowptr[wid], end = d_rowptr[wid + 1];
    const uint2* EG = reinterpret_cast<const uint2*>(d_EGO16);

    // ---- pass 1: Z1 row accumulate (halves, unroll-2, no shfl inside) ----
    float4 acc = make_float4(0, 0, 0, 0);
    int j = start + half;
    for (; j + 2 < end; j += 4) {
        int t0 = __ldg(&d_sorted_t[j]);
        int t1 = __ldg(&d_sorted_t[j + 2]);
        float4 s0 = h4_to_f4(__ldg(&EG[(size_t)t0 * 16 + c]));
        float4 s1 = h4_to_f4(__ldg(&EG[(size_t)t1 * 16 + c]));
        acc.x += s0.x + s1.x; acc.y += s0.y + s1.y;
        acc.z += s0.z + s1.z; acc.w += s0.w + s1.w;
    }
    if (j < end) {
        int t = __ldg(&d_sorted_t[j]);
        float4 s = h4_to_f4(__ldg(&EG[(size_t)t * 16 + c]));
        acc.x += s.x; acc.y += s.y; acc.z += s.z; acc.w += s.w;
    }
    acc.x += __shfl_xor_sync(0xffffffffu, acc.x, 16);
    acc.y += __shfl_xor_sync(0xffffffffu, acc.y, 16);
    acc.z += __shfl_xor_sync(0xffffffffu, acc.z, 16);
    acc.w += __shfl_xor_sync(0xffffffffu, acc.w, 16);
    float ss = acc.x * acc.x + acc.y * acc.y + acc.z * acc.z + acc.w * acc.w;
    ss += __shfl_xor_sync(0xffffffffu, ss, 1);
    ss += __shfl_xor_sync(0xffffffffu, ss, 2);
    float ih = rsqrtf(fmaxf(ss, 1e-12f));
    float4 hvf = make_float4(acc.x * ih, acc.y * ih, acc.z * ih, acc.w * ih);
    // lane c now holds global channels 4c..4c+3 (intent c>>2), replicated in both halves

    // ---- transpose hv into (slot,intent) layout: lane = 4*slot + intent ----
    int slot = lane >> 2, it = lane & 3;
    float hv[16];
#pragma unroll
    for (int k = 0; k < 16; k++) {
        int src = it * 4 + (k >> 2);        // chunk holding channel k of intent it
        float v;
        switch (k & 3) {                     // static component select
            case 0: v = __shfl_sync(0xffffffffu, hvf.x, src); break;
            case 1: v = __shfl_sync(0xffffffffu, hvf.y, src); break;
            case 2: v = __shfl_sync(0xffffffffu, hvf.z, src); break;
            default: v = __shfl_sync(0xffffffffu, hvf.w, src); break;
        }
        hv[k] = v;
    }

    // ---- pass 2: 8 edges per warp-iteration; lane handles (edge slot, intent) ----
    float dsum = 0.f;
    for (int base = start; base < end; base += 8) {
        int j2 = base + slot;
        bool act = (j2 < end);               // uniform within each 4-lane quad
        int t = act ? __ldg(&d_sorted_t[j2]) : 0;
        const uint4* bp = reinterpret_cast<const uint4*>(d_TT16 + ((size_t)t << 6)) + (it << 1);
        uint4 q0 = __ldg(bp);
        uint4 q1 = __ldg(bp + 1);
        unsigned wreg[8] = {q0.x, q0.y, q0.z, q0.w, q1.x, q1.y, q1.z, q1.w};
        float p = 0.f;
#pragma unroll
        for (int k = 0; k < 8; k++) {
            float2 f = __half22float2(*reinterpret_cast<const __half2*>(&wreg[k]));
            p = fmaf(f.x, hv[2 * k], p);
            p = fmaf(f.y, hv[2 * k + 1], p);
        }
        // softmax over the 4 intents of this edge (quad = bits 0,1); "1+" & max cancel
        float ex = __expf(p);
        float sum = ex + __shfl_xor_sync(0xffffffffu, ex, 1);
        sum += __shfl_xor_sync(0xffffffffu, sum, 2);
        float sc = __fdividef(ex, sum);
        if (act) {
            d_SC[(size_t)j2 * 4 + it] = sc;  // = base*4 + lane : fully coalesced
            dsum += sc;
        }
    }
    // reduce dsum over slots (bits 2,3,4)
    dsum += __shfl_xor_sync(0xffffffffu, dsum, 4);
    dsum += __shfl_xor_sync(0xffffffffu, dsum, 8);
    dsum += __shfl_xor_sync(0xffffffffu, dsum, 16);
    if (lane < 4)
        d_deg2[wid * 4 + it] = dsum;
}

// warp-per-row SpMM2 fused with rs2 (inline rsqrt) and final mean -> out. (R5 version)
__global__ void k_row2(const float* __restrict__ Gu, const float* __restrict__ Gi,
                       float* __restrict__ out) {
    int wid = (blockIdx.x * blockDim.x + threadIdx.x) >> 5;
    if (wid >= NN) return;
    int lane = threadIdx.x & 31, half = lane >> 4, c = lane & 15;
    int intent = c >> 2;
    int start = d_rowptr[wid], end = d_rowptr[wid + 1];
    float4 acc = make_float4(0, 0, 0, 0);
    int j = start + half;
    for (; j + 2 < end; j += 4) {
        int t0 = __ldg(&d_sorted_t[j]);
        int t1 = __ldg(&d_sorted_t[j + 2]);
        float w0 = __ldg(&d_SC[(size_t)j * 4 + intent]) *
                   rsqrtf(__ldg(&d_deg2[t0 * 4 + intent]));
        float w1 = __ldg(&d_SC[(size_t)(j + 2) * 4 + intent]) *
                   rsqrtf(__ldg(&d_deg2[t1 * 4 + intent]));
        float4 s0 = __ldg(&ego_row(Gu, Gi, t0)[c]);
        float4 s1 = __ldg(&ego_row(Gu, Gi, t1)[c]);
        acc.x += w0 * s0.x + w1 * s1.x;
        acc.y += w0 * s0.y + w1 * s1.y;
        acc.z += w0 * s0.z + w1 * s1.z;
        acc.w += w0 * s0.w + w1 * s1.w;
    }
    if (j < end) {
        int t = __ldg(&d_sorted_t[j]);
        float w = __ldg(&d_SC[(size_t)j * 4 + intent]) *
                  rsqrtf(__ldg(&d_deg2[t * 4 + intent]));
        float4 s = __ldg(&ego_row(Gu, Gi, t)[c]);
        acc.x += w * s.x; acc.y += w * s.y; acc.z += w * s.z; acc.w += w * s.w;
    }
    acc.x += __shfl_xor_sync(0xffffffffu, acc.x, 16);
    acc.y += __shfl_xor_sync(0xffffffffu, acc.y, 16);
    acc.z += __shfl_xor_sync(0xffffffffu, acc.z, 16);
    acc.w += __shfl_xor_sync(0xffffffffu, acc.w, 16);
    if (half == 0) {
        float r2 = rsqrtf(d_deg2[wid * 4 + intent]);
        float4 a = __ldg(&ego_row(Gu, Gi, wid)[c]);
        reinterpret_cast<float4*>(out)[(size_t)wid * 16 + c] =
            make_float4(0.5f * (a.x + r2 * acc.x), 0.5f * (a.y + r2 * acc.y),
                        0.5f * (a.z + r2 * acc.z), 0.5f * (a.w + r2 * acc.w));
    }
}

extern "C" void kernel_launch(void* const* d_in, const int* in_sizes, int n_in,
                              void* d_out, int out_size) {
    const float* Gu = (const float*)d_in[0];
    const float* Gi = (const float*)d_in[1];
    const int*   eh = (const int*)d_in[2];
    const int*   et = (const int*)d_in[3];
    float* out = (float*)d_out;

    void* degp = nullptr;
    cudaGetSymbolAddress(&degp, d_deg);
    cudaMemsetAsync(degp, 0, NN * sizeof(int));

    const int T = 256;
    const int ROWG = (NN * 32 + T - 1) / T;   // warp-per-row grids
    k_deg         <<<(EE / 4 + T - 1) / T, T>>>(eh);
    k_s1          <<<NB, 256>>>();
    k_scan        <<<NB, 256>>>();
    k_scatter_node<<<SCAT_BLKS + NODE_BLKS, T>>>(eh, et, Gu, Gi);
    k_row1attn    <<<ROWG, T>>>();
    k_row2        <<<ROWG, T>>>(Gu, Gi, out);
}

// round 9
// speedup vs baseline: 1.2958x; 1.0018x over previous
#include <cuda_runtime.h>
#include <cuda_fp16.h>

#define NUM_USERS 30000
#define NN 60000            // total nodes
#define EE 800000           // edges
#define KK 64               // embed dim (4 intents x 16)
#define NB 235              // ceil(NN/256) scan blocks

// -------- device scratch --------
__device__ __half d_TT16[(size_t)NN * KK];   // fp16 tanh(per-intent l2norm(ego))
__device__ __half d_EGO16[(size_t)NN * KK];  // fp16 ego[n]/sqrt(deg[n])
__device__ float  d_SC[(size_t)EE * 4];      // softmax scores at SORTED edge pos
__device__ int    d_deg[NN];
__device__ float  d_ratio[NN * 4];           // sqrt(deg[n]) * rsqrt(deg2[n,intent])
__device__ int    d_rowptr[NN + 1];
__device__ int    d_cursor[NN];
__device__ int    d_sorted_t[EE];            // tails grouped by head
__device__ int    d_partial[256];            // scan block sums

__device__ __forceinline__ const float4* ego_row(const float* Gu, const float* Gi, int t) {
    const float* p = (t < NUM_USERS) ? (Gu + (size_t)t * KK)
                                     : (Gi + (size_t)(t - NUM_USERS) * KK);
    return reinterpret_cast<const float4*>(p);
}

__device__ __forceinline__ float4 h4_to_f4(uint2 p) {
    float2 a = __half22float2(*reinterpret_cast<const __half2*>(&p.x));
    float2 b = __half22float2(*reinterpret_cast<const __half2*>(&p.y));
    return make_float4(a.x, a.y, b.x, b.y);
}

__device__ __forceinline__ float fast_tanh(float x) {   // |x|<=1 here
    float e = __expf(2.f * x);
    return __fdividef(e - 1.f, e + 1.f);
}

// block-wide exclusive scan of one int per thread (blockDim=256)
__device__ __forceinline__ int block_exscan(int v, int* sm) {
    int lane = threadIdx.x & 31, w = threadIdx.x >> 5;
    int x = v;
#pragma unroll
    for (int d = 1; d < 32; d <<= 1) {
        int y = __shfl_up_sync(0xffffffffu, x, d);
        if (lane >= d) x += y;
    }
    if (lane == 31) sm[w] = x;
    __syncthreads();
    if (w == 0) {
        int s = (lane < 8) ? sm[lane] : 0;
#pragma unroll
        for (int d = 1; d < 8; d <<= 1) {
            int y = __shfl_up_sync(0xffffffffu, s, d);
            if (lane >= d) s += y;
        }
        if (lane < 8) sm[lane] = s;
    }
    __syncthreads();
    int off = (w > 0) ? sm[w - 1] : 0;
    return off + x - v;
}

// -------- kernels --------

#define DEG_BLKS  ((EE / 4 + 255) / 256)
#define SCAT_BLKS ((EE / 4 + 255) / 256)
#define NODE_BLKS ((NN * 16 + 255) / 256)

// fused: blocks [0, DEG_BLKS) count head degrees; rest compute TT16 (no deg dep)
__global__ void k_deg_tt(const int* __restrict__ eh,
                         const float* __restrict__ Gu, const float* __restrict__ Gi) {
    if (blockIdx.x < DEG_BLKS) {
        int g = blockIdx.x * blockDim.x + threadIdx.x;
        if (g >= EE / 4) return;
        int4 h4 = __ldg(&reinterpret_cast<const int4*>(eh)[g]);
        atomicAdd(&d_deg[h4.x], 1);
        atomicAdd(&d_deg[h4.y], 1);
        atomicAdd(&d_deg[h4.z], 1);
        atomicAdd(&d_deg[h4.w], 1);
    } else {
        int tid = (blockIdx.x - DEG_BLKS) * blockDim.x + threadIdx.x;
        if (tid >= NN * 16) return;
        int n = tid >> 4;
        float4 v = __ldg(&ego_row(Gu, Gi, n)[tid & 15]);
        float ss = v.x * v.x + v.y * v.y + v.z * v.z + v.w * v.w;
        ss += __shfl_xor_sync(0xffffffffu, ss, 1);
        ss += __shfl_xor_sync(0xffffffffu, ss, 2);
        float it = rsqrtf(fmaxf(ss, 1e-12f));
        __half2 t0 = __floats2half2_rn(fast_tanh(v.x * it), fast_tanh(v.y * it));
        __half2 t1 = __floats2half2_rn(fast_tanh(v.z * it), fast_tanh(v.w * it));
        uint2 tp; tp.x = *reinterpret_cast<unsigned*>(&t0);
                  tp.y = *reinterpret_cast<unsigned*>(&t1);
        reinterpret_cast<uint2*>(d_TT16)[tid] = tp;
    }
}

__global__ void k_s1() {
    __shared__ int sm[8];
    int i = blockIdx.x * 256 + threadIdx.x;
    int v = (i < NN) ? d_deg[i] : 0;
    int ex = block_exscan(v, sm);
    if (threadIdx.x == 255) d_partial[blockIdx.x] = ex + v;
}

__global__ void k_scan() {
    __shared__ int sm[8];
    __shared__ int base_sh;
    if (threadIdx.x < 32) {
        int s = 0;
        for (int t = threadIdx.x; t < blockIdx.x; t += 32) s += d_partial[t];
#pragma unroll
        for (int d = 16; d >= 1; d >>= 1) s += __shfl_xor_sync(0xffffffffu, s, d);
        if (threadIdx.x == 0) base_sh = s;
    }
    int i = blockIdx.x * 256 + threadIdx.x;
    int v = (i < NN) ? d_deg[i] : 0;
    int ex = block_exscan(v, sm);           // has __syncthreads (publishes base_sh)
    ex += base_sh;
    if (i < NN) { d_rowptr[i] = ex; d_cursor[i] = ex; }
    if (i == NN - 1) d_rowptr[NN] = EE;
}

// fused: blocks [0, SCAT_BLKS) scatter tails; rest compute EGO16 (needs deg)
__global__ void k_scatter_ego(const int* __restrict__ eh, const int* __restrict__ et,
                              const float* __restrict__ Gu, const float* __restrict__ Gi) {
    if (blockIdx.x < SCAT_BLKS) {
        int g = blockIdx.x * blockDim.x + threadIdx.x;
        if (g >= EE / 4) return;
        int4 h4 = __ldg(&reinterpret_cast<const int4*>(eh)[g]);
        int4 t4 = __ldg(&reinterpret_cast<const int4*>(et)[g]);
        d_sorted_t[atomicAdd(&d_cursor[h4.x], 1)] = t4.x;
        d_sorted_t[atomicAdd(&d_cursor[h4.y], 1)] = t4.y;
        d_sorted_t[atomicAdd(&d_cursor[h4.z], 1)] = t4.z;
        d_sorted_t[atomicAdd(&d_cursor[h4.w], 1)] = t4.w;
    } else {
        int tid = (blockIdx.x - SCAT_BLKS) * blockDim.x + threadIdx.x;
        if (tid >= NN * 16) return;
        int n = tid >> 4;
        float4 v = __ldg(&ego_row(Gu, Gi, n)[tid & 15]);
        float w = rsqrtf((float)d_deg[n]);   // rs1 folded into EGO16
        __half2 e0 = __floats2half2_rn(w * v.x, w * v.y);
        __half2 e1 = __floats2half2_rn(w * v.z, w * v.w);
        uint2 ep; ep.x = *reinterpret_cast<unsigned*>(&e0);
                  ep.y = *reinterpret_cast<unsigned*>(&e1);
        reinterpret_cast<uint2*>(d_EGO16)[tid] = ep;
    }
}

// Warp-per-row: SpMM1 (halves layout) -> per-intent l2norm -> transpose hv ->
// attention in (slot,intent) layout -> ratio[n,i] = sqrt(deg)*rsqrt(deg2).
__global__ void k_row1attn() {
    int wid = (blockIdx.x * blockDim.x + threadIdx.x) >> 5;
    if (wid >= NN) return;
    int lane = threadIdx.x & 31, half = lane >> 4, c = lane & 15;
    int start = d_rowptr[wid], end = d_rowptr[wid + 1];
    const uint2* EG = reinterpret_cast<const uint2*>(d_EGO16);

    // ---- pass 1: Z1 row accumulate ----
    float4 acc = make_float4(0, 0, 0, 0);
    int j = start + half;
    for (; j + 2 < end; j += 4) {
        int t0 = __ldg(&d_sorted_t[j]);
        int t1 = __ldg(&d_sorted_t[j + 2]);
        float4 s0 = h4_to_f4(__ldg(&EG[(size_t)t0 * 16 + c]));
        float4 s1 = h4_to_f4(__ldg(&EG[(size_t)t1 * 16 + c]));
        acc.x += s0.x + s1.x; acc.y += s0.y + s1.y;
        acc.z += s0.z + s1.z; acc.w += s0.w + s1.w;
    }
    if (j < end) {
        int t = __ldg(&d_sorted_t[j]);
        float4 s = h4_to_f4(__ldg(&EG[(size_t)t * 16 + c]));
        acc.x += s.x; acc.y += s.y; acc.z += s.z; acc.w += s.w;
    }
    acc.x += __shfl_xor_sync(0xffffffffu, acc.x, 16);
    acc.y += __shfl_xor_sync(0xffffffffu, acc.y, 16);
    acc.z += __shfl_xor_sync(0xffffffffu, acc.z, 16);
    acc.w += __shfl_xor_sync(0xffffffffu, acc.w, 16);
    float ss = acc.x * acc.x + acc.y * acc.y + acc.z * acc.z + acc.w * acc.w;
    ss += __shfl_xor_sync(0xffffffffu, ss, 1);
    ss += __shfl_xor_sync(0xffffffffu, ss, 2);
    float ih = rsqrtf(fmaxf(ss, 1e-12f));
    float4 hvf = make_float4(acc.x * ih, acc.y * ih, acc.z * ih, acc.w * ih);

    // ---- transpose hv into (slot,intent) layout: lane = 4*slot + intent ----
    int slot = lane >> 2, it = lane & 3;
    float hv[16];
#pragma unroll
    for (int k = 0; k < 16; k++) {
        int src = it * 4 + (k >> 2);
        float v;
        switch (k & 3) {
            case 0: v = __shfl_sync(0xffffffffu, hvf.x, src); break;
            case 1: v = __shfl_sync(0xffffffffu, hvf.y, src); break;
            case 2: v = __shfl_sync(0xffffffffu, hvf.z, src); break;
            default: v = __shfl_sync(0xffffffffu, hvf.w, src); break;
        }
        hv[k] = v;
    }

    // ---- pass 2: 8 edges per warp-iteration; lane = (edge slot, intent) ----
    float dsum = 0.f;
    for (int base = start; base < end; base += 8) {
        int j2 = base + slot;
        bool act = (j2 < end);
        int t = act ? __ldg(&d_sorted_t[j2]) : 0;
        const uint4* bp = reinterpret_cast<const uint4*>(d_TT16 + ((size_t)t << 6)) + (it << 1);
        uint4 q0 = __ldg(bp);
        uint4 q1 = __ldg(bp + 1);
        unsigned wreg[8] = {q0.x, q0.y, q0.z, q0.w, q1.x, q1.y, q1.z, q1.w};
        float p = 0.f;
#pragma unroll
        for (int k = 0; k < 8; k++) {
            float2 f = __half22float2(*reinterpret_cast<const __half2*>(&wreg[k]));
            p = fmaf(f.x, hv[2 * k], p);
            p = fmaf(f.y, hv[2 * k + 1], p);
        }
        float ex = __expf(p);                          // "1+" & max-shift cancel
        float sum = ex + __shfl_xor_sync(0xffffffffu, ex, 1);
        sum += __shfl_xor_sync(0xffffffffu, sum, 2);
        float sc = __fdividef(ex, sum);
        if (act) {
            d_SC[(size_t)j2 * 4 + it] = sc;            // coalesced
            dsum += sc;
        }
    }
    dsum += __shfl_xor_sync(0xffffffffu, dsum, 4);
    dsum += __shfl_xor_sync(0xffffffffu, dsum, 8);
    dsum += __shfl_xor_sync(0xffffffffu, dsum, 16);
    if (lane < 4)
        d_ratio[wid * 4 + it] = sqrtf((float)(end - start)) * rsqrtf(dsum);
}

// warp-per-row SpMM2 on fp16 ego (weight re-derivation makes it exact vs rs2 form):
//   w = SC[j] * ratio[t]  with  EGO16[t] = ego[t]/sqrt(deg[t])
//     = SC[j] * rsqrt(deg2[t]) * ego[t]        (the original formula)
__global__ void k_row2(const float* __restrict__ Gu, const float* __restrict__ Gi,
                       float* __restrict__ out) {
    int wid = (blockIdx.x * blockDim.x + threadIdx.x) >> 5;
    if (wid >= NN) return;
    int lane = threadIdx.x & 31, half = lane >> 4, c = lane & 15;
    int intent = c >> 2;
    int start = d_rowptr[wid], end = d_rowptr[wid + 1];
    const uint2* EG = reinterpret_cast<const uint2*>(d_EGO16);
    float4 acc = make_float4(0, 0, 0, 0);
    int j = start + half;
    for (; j + 2 < end; j += 4) {
        int t0 = __ldg(&d_sorted_t[j]);
        int t1 = __ldg(&d_sorted_t[j + 2]);
        float w0 = __ldg(&d_SC[(size_t)j * 4 + intent]) * __ldg(&d_ratio[t0 * 4 + intent]);
        float w1 = __ldg(&d_SC[(size_t)(j + 2) * 4 + intent]) * __ldg(&d_ratio[t1 * 4 + intent]);
        float4 s0 = h4_to_f4(__ldg(&EG[(size_t)t0 * 16 + c]));
        float4 s1 = h4_to_f4(__ldg(&EG[(size_t)t1 * 16 + c]));
        acc.x += w0 * s0.x + w1 * s1.x;
        acc.y += w0 * s0.y + w1 * s1.y;
        acc.z += w0 * s0.z + w1 * s1.z;
        acc.w += w0 * s0.w + w1 * s1.w;
    }
    if (j < end) {
        int t = __ldg(&d_sorted_t[j]);
        float w = __ldg(&d_SC[(size_t)j * 4 + intent]) * __ldg(&d_ratio[t * 4 + intent]);
        float4 s = h4_to_f4(__ldg(&EG[(size_t)t * 16 + c]));
        acc.x += w * s.x; acc.y += w * s.y; acc.z += w * s.z; acc.w += w * s.w;
    }
    acc.x += __shfl_xor_sync(0xffffffffu, acc.x, 16);
    acc.y += __shfl_xor_sync(0xffffffffu, acc.y, 16);
    acc.z += __shfl_xor_sync(0xffffffffu, acc.z, 16);
    acc.w += __shfl_xor_sync(0xffffffffu, acc.w, 16);
    if (half == 0) {
        // rs2[wid] = rsqrt(deg2[wid]) = ratio[wid] / sqrt(deg[wid])
        float r2 = d_ratio[wid * 4 + intent] * rsqrtf((float)(end - start));
        float4 a = __ldg(&ego_row(Gu, Gi, wid)[c]);   // self term stays fp32
        reinterpret_cast<float4*>(out)[(size_t)wid * 16 + c] =
            make_float4(0.5f * (a.x + r2 * acc.x), 0.5f * (a.y + r2 * acc.y),
                        0.5f * (a.z + r2 * acc.z), 0.5f * (a.w + r2 * acc.w));
    }
}

extern "C" void kernel_launch(void* const* d_in, const int* in_sizes, int n_in,
                              void* d_out, int out_size) {
    const float* Gu = (const float*)d_in[0];
    const float* Gi = (const float*)d_in[1];
    const int*   eh = (const int*)d_in[2];
    const int*   et = (const int*)d_in[3];
    float* out = (float*)d_out;

    void* degp = nullptr;
    cudaGetSymbolAddress(&degp, d_deg);
    cudaMemsetAsync(degp, 0, NN * sizeof(int));

    const int T = 256;
    const int ROWG = (NN * 32 + T - 1) / T;   // warp-per-row grids
    k_deg_tt     <<<DEG_BLKS + NODE_BLKS, T>>>(eh, Gu, Gi);
    k_s1         <<<NB, 256>>>();
    k_scan       <<<NB, 256>>>();
    k_scatter_ego<<<SCAT_BLKS + NODE_BLKS, T>>>(eh, et, Gu, Gi);
    k_row1attn   <<<ROWG, T>>>();
    k_row2       <<<ROWG, T>>>(Gu, Gi, out);
}